// round 17
// baseline (speedup 1.0000x reference)
#include <cuda_runtime.h>

#define D_  64
#define H_  512
#define W_  512
#define NB  2
#define HW  (H_*W_)                 // 262144
#define NT  (NB*D_*H_*W_)           // 33554432
#define PAD 5
#define KS  11
#define CH  64                      // H rows per warp strip
#define WC  32                      // W columns per warp strip
#define WE  (WC + 2*PAD)            // staged elements per row: 42
#define WEP 44                      // padded stride
#define NROWS (CH + 2*PAD)          // 74 input rows per strip

typedef unsigned long long u64;

// Scratch after W+H blur: float4 plane (x,y,xx,yy) + scalar plane (xy).
__device__ float4 g_s4[(size_t)NT];
__device__ float  g_s1[(size_t)NT];
__device__ double g_acc;

// Gaussian(sigma=1.5, k=11) weights as compile-time literals (FFMA-imm, rt=1).
#define WG0 0.00102838f
#define WG1 0.00759873f
#define WG2 0.03600077f
#define WG3 0.10936071f
#define WG4 0.21300554f
#define WG5 0.26601173f
#define GSC(k) ((k)==0||(k)==10 ? WG0 : (k)==1||(k)==9 ? WG1 : \
                (k)==2||(k)==8  ? WG2 : (k)==3||(k)==7 ? WG3 : \
                (k)==4||(k)==6  ? WG4 : WG5)
#define GSYM(t) ((t) <= 5 ? (t) : 10 - (t))

// ---- packed f32x2 helpers ---------------------------------------------------
__device__ __forceinline__ u64 pk2(float lo, float hi) {
    u64 r; asm("mov.b64 %0, {%1, %2};" : "=l"(r) : "f"(lo), "f"(hi)); return r;
}
__device__ __forceinline__ void upk2(u64 v, float& lo, float& hi) {
    asm("mov.b64 {%0, %1}, %2;" : "=f"(lo), "=f"(hi) : "l"(v));
}
__device__ __forceinline__ u64 fma2(u64 a, u64 b, u64 c) {
    u64 d; asm("fma.rn.f32x2 %0, %1, %2, %3;" : "=l"(d) : "l"(a), "l"(b), "l"(c));
    return d;
}
__device__ __forceinline__ u64 mul2(u64 a, u64 b) {
    u64 d; asm("mul.rn.f32x2 %0, %1, %2;" : "=l"(d) : "l"(a), "l"(b));
    return d;
}

// ---- cp.async helpers -------------------------------------------------------
__device__ __forceinline__ void cpa4(void* dst_smem, const void* src) {
    unsigned sa = (unsigned)__cvta_generic_to_shared(dst_smem);
    asm volatile("cp.async.ca.shared.global [%0], [%1], 4;" :: "r"(sa), "l"(src));
}
#define CPA_COMMIT() asm volatile("cp.async.commit_group;" ::: "memory")
#define CPA_WAIT1()  asm volatile("cp.async.wait_group 1;" ::: "memory")

// ---------------------------------------------------------------------------
__global__ void k_zero_acc() { g_acc = 0.0; }
__global__ void k_noop1() {}
__global__ void k_noop2() {}

// ---------------------------------------------------------------------------
// Fused W+H blur, WARP-AUTONOMOUS: each warp owns a 32-col x 64-row strip of
// one (n,d) slice and stages its own haloed 42-elem row segments (x,y) into
// private smem via a 3-stage cp.async pipeline. NO __syncthreads — only
// __syncwarp per row, so the 8 warps of a block (and both co-resident blocks)
// run fully independently and fill each other's stall bubbles.
//
// W-blur with packed f32x2; scatter-accumulate into 11 pending H outputs in
// packed registers (unroll-by-11 => static slots). Slot protocol: output h
// lives in slot (h-h0) mod 11; at row j the k=10 term is the FIRST
// contribution of output h0+j (weight g[0], slot u=j%11) and is an ASSIGNMENT.
__global__ void __launch_bounds__(256, 2) k_wh(const float* __restrict__ x,
                                               const float* __restrict__ y) {
    __shared__ float sb[8][3][2][WEP];   // [warp][stage][field][elem]
    int wid  = threadIdx.x >> 5;
    int lane = threadIdx.x & 31;
    int gwarp = blockIdx.x * 8 + wid;
    int cs = gwarp & 15;            // col strip (16 per row)
    int hc = (gwarp >> 4) & 7;      // h strip (8)
    int nd = gwarp >> 7;            // slice (n*D_+d, 128)
    int c0 = cs << 5;
    int h0 = hc << 6;
    size_t slice = (size_t)nd * HW;

    const float* xsl = x + slice;
    const float* ysl = y + slice;

    u64 gg6[6];
    gg6[0] = pk2(WG0, WG0); gg6[1] = pk2(WG1, WG1); gg6[2] = pk2(WG2, WG2);
    gg6[3] = pk2(WG3, WG3); gg6[4] = pk2(WG4, WG4); gg6[5] = pk2(WG5, WG5);

    u64 acc01[11], acc23[11];
    float acc4[11];
#pragma unroll
    for (int s = 0; s < 11; s++) { acc01[s] = 0; acc23[s] = 0; acc4[s] = 0.f; }

    // Element->global-col map (replicate clamp at volume edges).
    int gc0 = c0 - PAD + lane;                       // element e = lane
    gc0 = gc0 < 0 ? 0 : gc0;                         // (left edge only)
    int gc1 = c0 - PAD + lane + 32;                  // element e = lane+32
    gc1 = gc1 > W_ - 1 ? W_ - 1 : gc1;               // (right edge only)
    bool tail = (lane < WE - 32);                    // lanes 0..9

    auto stage = [&](int j) {
        int s = j % 3;
        int r = h0 - PAD + j;
        int rr = r < 0 ? 0 : (r > H_ - 1 ? H_ - 1 : r);
        const float* xr = xsl + (size_t)rr * W_;
        const float* yr = ysl + (size_t)rr * W_;
        cpa4(&sb[wid][s][0][lane], xr + gc0);
        cpa4(&sb[wid][s][1][lane], yr + gc0);
        if (tail) {
            cpa4(&sb[wid][s][0][lane + 32], xr + gc1);
            cpa4(&sb[wid][s][1][lane + 32], yr + gc1);
        }
    };

    // Prologue: rows 0 and 1 in flight.
    stage(0); CPA_COMMIT();
    stage(1); CPA_COMMIT();

    int wcol = c0 + lane;           // this thread's output column

    // Input rows j = 0..73, padded to 77 for the unroll-by-11.
#pragma unroll 1
    for (int jb = 0; jb < 77; jb += 11) {
#pragma unroll
        for (int u = 0; u < 11; u++) {
            int j = jb + u;
            if (j < NROWS) {
                CPA_WAIT1();                  // row j's group complete
                __syncwarp();                 // visible warp-wide
                if (j + 2 < NROWS) stage(j + 2);
                CPA_COMMIT();                 // uniform group accounting

                const float* xrow = sb[wid][j % 3][0];
                const float* yrow = sb[wid][j % 3][1];

                // W-blur of the 5 product fields (packed: (sx,sy),(sxx,syy)).
                u64 s01 = 0, s23 = 0;
                float s4 = 0.f;
#pragma unroll
                for (int k = 0; k < KS; k++) {
                    float xv = xrow[lane + k];
                    float yv = yrow[lane + k];
                    u64 p  = pk2(xv, yv);
                    u64 g2 = gg6[GSYM(k)];
                    s01 = fma2(g2, p, s01);
                    s23 = fma2(g2, mul2(p, p), s23);
                    s4  = fmaf(xv * yv, GSC(k), s4);   // FFMA-imm
                }

                // Row feeds outputs h = r-5+k with weight g[10-k];
                // slot(h) = (u + k + 1) mod 11 (static).
#pragma unroll
                for (int k = 0; k < 10; k++) {
                    int s = (u + k + 1) % 11;
                    u64 g2 = gg6[GSYM(10 - k)];
                    acc01[s] = fma2(g2, s01, acc01[s]);
                    acc23[s] = fma2(g2, s23, acc23[s]);
                    acc4[s]  = fmaf(s4, GSC(10 - k), acc4[s]);  // FFMA-imm
                }
                // k = 10: first contribution of output h0+j -> ASSIGN slot u.
                acc01[u] = mul2(gg6[0], s01);
                acc23[u] = mul2(gg6[0], s23);
                acc4[u]  = WG0 * s4;

                // Output h = h0+j-10 completes at this row (slot (u+1)%11).
                if (j >= 10) {
                    int h = h0 + j - 10;
                    int s = (u + 1) % 11;
                    size_t o = slice + (size_t)h * W_ + wcol;
                    float a0, a1, a2, a3;
                    upk2(acc01[s], a0, a1);
                    upk2(acc23[s], a2, a3);
                    __stcs(&g_s4[o], make_float4(a0, a1, a2, a3));
                    __stcs(&g_s1[o], acc4[s]);
                }
            }
        }
    }
}

// ---------------------------------------------------------------------------
// D-pass: rotating register window (slots static via unroll-by-11), fused SSIM
// map + mean reduction. 2 wide loads per iteration (.128 + .32); FFMA-imm taps.
__global__ void __launch_bounds__(256) k_pass_d() {
    int col = blockIdx.x * blockDim.x + threadIdx.x;   // 0 .. NB*HW-1
    int n   = col >> 18;            // / HW
    int hw  = col & (HW - 1);
    size_t base = (size_t)n * D_ * HW + hw;

    const float c1 = 0.01f * 0.01f;
    const float c2 = 0.03f * 0.03f;

    // At iteration d, window element k (depth d-5+k) lives in slot (d+k)%11.
    float4 win4[KS];
    float  win1[KS];
#pragma unroll
    for (int k = 0; k < KS; k++) {
        int dj = k - PAD;
        dj = dj < 0 ? 0 : dj;
        size_t off = base + (size_t)dj * HW;
        win4[k] = __ldcs(&g_s4[off]);
        win1[k] = __ldcs(&g_s1[off]);
    }

    float lsum = 0.f;
#pragma unroll 1
    for (int dbase = 0; dbase < 66; dbase += 11) {
#pragma unroll
        for (int u = 0; u < 11; u++) {
            int d = dbase + u;
            float s0 = 0.f, s1 = 0.f, s2 = 0.f, s3 = 0.f, s4 = 0.f;
#pragma unroll
            for (int k = 0; k < KS; k++) {
                int s = (u + k) % 11;          // static
                s0 = fmaf(win4[s].x, GSC(k), s0);
                s1 = fmaf(win4[s].y, GSC(k), s1);
                s2 = fmaf(win4[s].z, GSC(k), s2);
                s3 = fmaf(win4[s].w, GSC(k), s3);
                s4 = fmaf(win1[s],   GSC(k), s4);
            }
            float mu_x = s0, mu_y = s1;
            float mu_x2 = mu_x * mu_x;
            float mu_y2 = mu_y * mu_y;
            float mu_xy = mu_x * mu_y;
            float sig_x  = fmaxf(s2 - mu_x2, 0.f);
            float sig_y  = fmaxf(s3 - mu_y2, 0.f);
            float sig_xy = s4 - mu_xy;
            float num = (2.f * mu_xy + c1) * (2.f * sig_xy + c2);
            float den = (mu_x2 + mu_y2 + c1) * (sig_x + sig_y + c2);
            if (d < D_) lsum += num / den;

            // Replace oldest (depth d-5, slot d%11 == u) with depth d+6.
            int dn = d + PAD + 1;
            dn = dn > D_ - 1 ? D_ - 1 : dn;
            size_t off = base + (size_t)dn * HW;
            win4[u] = __ldcs(&g_s4[off]);
            win1[u] = __ldcs(&g_s1[off]);
        }
    }

    // block reduction
    unsigned lane = threadIdx.x & 31;
    unsigned wid  = threadIdx.x >> 5;
#pragma unroll
    for (int o = 16; o > 0; o >>= 1)
        lsum += __shfl_xor_sync(0xffffffffu, lsum, o);
    __shared__ float ws[8];
    if (lane == 0) ws[wid] = lsum;
    __syncthreads();
    if (wid == 0) {
        float v = lane < (blockDim.x >> 5) ? ws[lane] : 0.f;
#pragma unroll
        for (int o = 4; o > 0; o >>= 1)
            v += __shfl_xor_sync(0xffffffffu, v, o);
        if (lane == 0) atomicAdd(&g_acc, (double)v);
    }
}

// ---------------------------------------------------------------------------
__global__ void k_finalize(float* __restrict__ out, int n) {
    double mean = g_acc / (double)NT;
    for (int i = threadIdx.x; i < n; i += blockDim.x)
        out[i] = (float)mean;
}

// ---------------------------------------------------------------------------
extern "C" void kernel_launch(void* const* d_in, const int* in_sizes, int n_in,
                              void* d_out, int out_size) {
    const float* x = (const float*)d_in[0];
    const float* y = (const float*)d_in[1];
    float* out = (float*)d_out;

    k_zero_acc<<<1, 1>>>();
    k_noop1<<<1, 32>>>();           // keep ncu's fixed capture slot (idx 3)
    k_noop2<<<1, 32>>>();           // on k_wh
    k_wh<<<NB * D_ * (H_ / CH) * (W_ / WC) / 8, 256>>>(x, y);
    k_pass_d<<<(NB * HW) / 256, 256>>>();
    k_finalize<<<1, 32>>>(out, out_size);
}